// round 15
// baseline (speedup 1.0000x reference)
#include <cuda_runtime.h>
#include <cuda_fp16.h>
#include <cstdint>
#include <math.h>

namespace {
constexpr int B_  = 4;
constexpr int T_  = 2048;
constexpr int DM_ = 1024;
constexpr int H_  = 16;
constexpr int DH_ = 64;
constexpr int M_  = B_ * T_;     // 8192

// Scratch (device globals: allocation-free rule). fp16.
__device__ __half g_x  [(size_t)M_ * DM_];
__device__ __half g_wqT[(size_t)DM_ * DM_];  // [n][k]
__device__ __half g_wkT[(size_t)DM_ * DM_];
__device__ __half g_wvT[(size_t)DM_ * DM_];
__device__ __half g_woT[(size_t)DM_ * DM_];
__device__ __half g_q  [(size_t)M_ * DM_];   // [B,H,T,64]
__device__ __half g_k  [(size_t)M_ * DM_];
__device__ __half g_v  [(size_t)M_ * DM_];   // [B,H,64,T] (transposed for PV)
__device__ __half g_o  [(size_t)M_ * DM_];   // [B,T,H*64]

__device__ __forceinline__ float fexp2(float x) {
    float y;
    asm("ex2.approx.f32 %0, %1;" : "=f"(y) : "f"(x));
    return y;
}
__device__ __forceinline__ void mma_f16(float* c, const uint32_t* a, const uint32_t* b) {
    asm volatile(
        "mma.sync.aligned.m16n8k16.row.col.f32.f16.f16.f32 "
        "{%0,%1,%2,%3}, {%4,%5,%6,%7}, {%8,%9}, {%0,%1,%2,%3};\n"
        : "+f"(c[0]), "+f"(c[1]), "+f"(c[2]), "+f"(c[3])
        : "r"(a[0]), "r"(a[1]), "r"(a[2]), "r"(a[3]), "r"(b[0]), "r"(b[1]));
}
__device__ __forceinline__ void ldsm4(uint32_t* r, uint32_t addr) {
    asm volatile("ldmatrix.sync.aligned.m8n8.x4.shared.b16 {%0,%1,%2,%3}, [%4];"
        : "=r"(r[0]), "=r"(r[1]), "=r"(r[2]), "=r"(r[3]) : "r"(addr));
}
__device__ __forceinline__ uint32_t pack_h2(float x, float y) {
    __half2 h = __floats2half2_rn(x, y);
    return *reinterpret_cast<uint32_t*>(&h);
}
__device__ __forceinline__ uint32_t smem_u32(const void* p) {
    return (uint32_t)__cvta_generic_to_shared(p);
}
__device__ __forceinline__ void cp16(uint32_t dst, const void* src) {
    asm volatile("cp.async.cg.shared.global [%0], [%1], 16;\n" :: "r"(dst), "l"(src));
}
__device__ __forceinline__ void cp_commit() {
    asm volatile("cp.async.commit_group;\n");
}
template <int N>
__device__ __forceinline__ void cp_wait() {
    asm volatile("cp.async.wait_group %0;\n" :: "n"(N));
}
__device__ __forceinline__ uint32_t sw128(uint32_t off) {
    return off ^ ((off >> 3) & 0x70);
}

// ---------------------------------------------------------------------------
// x -> g_x fp16
// ---------------------------------------------------------------------------
__global__ void __launch_bounds__(256) round_x(const float* __restrict__ in, int n4)
{
    int i = blockIdx.x * blockDim.x + threadIdx.x;
    if (i < n4) {
        float4 v = reinterpret_cast<const float4*>(in)[i];
        reinterpret_cast<__half2*>(g_x)[2 * i]     = __floats2half2_rn(v.x, v.y);
        reinterpret_cast<__half2*>(g_x)[2 * i + 1] = __floats2half2_rn(v.z, v.w);
    }
}

// ---------------------------------------------------------------------------
// ALL weight transposes fused: [K, N] -> [N, K] fp16.
// ---------------------------------------------------------------------------
__global__ void __launch_bounds__(256) transpose_all(
    const float* __restrict__ Wq, const float* __restrict__ Wk,
    const float* __restrict__ Wv, const float* __restrict__ Wo)
{
    __shared__ float tl[32][33];
    const int tx = threadIdx.x & 31, ty = threadIdx.x >> 5;
    const int bid = blockIdx.x;
    int which, h, d0, n0;
    if (bid < 3072) {
        which = bid >> 10;
        int r = bid & 1023;
        d0 = (r & 31) * 32;
        n0 = ((r >> 5) & 1) * 32;
        h  = r >> 6;
    } else {
        which = 3;
        int r = bid - 3072;
        d0 = (r & 31) * 32;
        n0 = (r >> 5) * 32;
        h  = 0;
    }
    const float* in = (which == 0) ? Wq : (which == 1) ? Wk :
                      (which == 2) ? Wv : Wo;
    __half* dst = (which == 0) ? g_wqT : (which == 1) ? g_wkT :
                  (which == 2) ? g_wvT : g_woT;
    const int ldn = (which == 3) ? DM_ : DH_;
    const float* src = (which == 3) ? in : in + (size_t)h * DM_ * DH_;

#pragma unroll
    for (int i = 0; i < 4; i++) {
        int d = d0 + ty + i * 8;
        tl[ty + i * 8][tx] = src[(size_t)d * ldn + n0 + tx];
    }
    __syncthreads();
    const int nb = (which == 3) ? n0 : (h * DH_ + n0);
#pragma unroll
    for (int i = 0; i < 4; i++) {
        int n = ty + i * 8;
        dst[(size_t)(nb + n) * DM_ + d0 + tx] = __float2half_rn(tl[tx][n]);
    }
}

// ---------------------------------------------------------------------------
// fp16 GEMM v6: CTA tile 128x256, warp tile 64x64 (2x4 warps), k-chunk 64,
// 3-stage cp.async, SW128 + ldmatrix. 8 LDSM per 32 HMMA.
// mode 0: QKV. grid (64, 4, 3). z: WqT/WkT/WvT -> g_q / g_k / g_v(transposed)
// mode 1: out projection. grid (64, 4, 1). X=g_o, W=g_woT, out fp32 + bias.
// ---------------------------------------------------------------------------
constexpr int NSTG = 3;
constexpr int GT_A      = 128 * 128;            // A tile 16 KB
constexpr int GT_B      = 256 * 128;            // B tile 32 KB
constexpr int GSTAGE_B  = GT_A + GT_B;          // 48 KB
constexpr int GEMM_SMEM = NSTG * GSTAGE_B;      // 144 KB
constexpr int CHUNK = 64;
constexpr int NCHUNK = DM_ / CHUNK;             // 16

__device__ __forceinline__ void gemm_load_chunk(
    uint32_t smBase, int buf, const __half* __restrict__ X, const __half* __restrict__ Wt,
    size_t mBase, int nBase, int k0, int tid)
{
    const uint32_t xb = smBase + buf * GSTAGE_B;
    const uint32_t wb = xb + GT_A;
#pragma unroll
    for (int i = 0; i < 4; i++) {
        int idx = tid + i * 256;
        int r = idx >> 3, c = idx & 7;
        cp16(xb + sw128(r * 128 + c * 16), X + (mBase + r) * DM_ + k0 + c * 8);
    }
#pragma unroll
    for (int i = 0; i < 8; i++) {
        int idx = tid + i * 256;
        int r = idx >> 3, c = idx & 7;
        cp16(wb + sw128(r * 128 + c * 16), Wt + (size_t)(nBase + r) * DM_ + k0 + c * 8);
    }
    cp_commit();
}

__global__ void __launch_bounds__(256) gemm6(
    int mode, const float* __restrict__ bias, float* __restrict__ out_param)
{
    extern __shared__ __half smh[];
    const uint32_t smBase = smem_u32(smh);
    const int tid  = threadIdx.x;
    const int lane = tid & 31, wid = tid >> 5;
    const int wm = wid >> 2, wn = wid & 3;                  // 2 x 4 warps
    const int g = lane >> 2, q = lane & 3;
    const int r7 = lane & 7, sub = lane >> 3;
    const uint32_t xm = (uint32_t)r7 << 4;
    const uint32_t aksel = (uint32_t)(sub >> 1) * 16;
    const uint32_t bksel = (uint32_t)(sub & 1) * 16;
    const size_t mBase = (size_t)blockIdx.x * 128;
    const int nBase = blockIdx.y * 256;
    const int z  = blockIdx.z;

    uint32_t rA[4], rB[4];
#pragma unroll
    for (int mi = 0; mi < 4; mi++)
        rA[mi] = (uint32_t)(wm * 64 + mi * 16 + r7 + (sub & 1) * 8) * 128;
#pragma unroll
    for (int t = 0; t < 4; t++)
        rB[t] = GT_A + (uint32_t)(wn * 64 + t * 16 + r7 + (sub >> 1) * 8) * 128;

    const __half* X  = (mode == 0) ? g_x : g_o;
    const __half* Wt = (mode == 0) ? ((z == 0) ? g_wqT : (z == 1) ? g_wkT : g_wvT) : g_woT;

    float acc[4][8][4];
#pragma unroll
    for (int i = 0; i < 4; i++)
#pragma unroll
        for (int j = 0; j < 8; j++)
#pragma unroll
            for (int r = 0; r < 4; r++) acc[i][j][r] = 0.f;

    gemm_load_chunk(smBase, 0, X, Wt, mBase, nBase, 0, tid);
    gemm_load_chunk(smBase, 1, X, Wt, mBase, nBase, CHUNK, tid);

#pragma unroll 1
    for (int i = 0; i < NCHUNK; i++) {
        if (i + 1 < NCHUNK) cp_wait<1>(); else cp_wait<0>();
        __syncthreads();
        if (i + 2 < NCHUNK)
            gemm_load_chunk(smBase, (i + 2) % NSTG, X, Wt, mBase, nBase, (i + 2) * CHUNK, tid);

        const uint32_t Xb = smBase + (i % NSTG) * GSTAGE_B;
#pragma unroll
        for (int ks = 0; ks < 4; ks++) {
            const uint32_t ka = (ks * 32 + aksel) ^ xm;
            const uint32_t kb = (ks * 32 + bksel) ^ xm;
            uint32_t a[4][4];
#pragma unroll
            for (int mi = 0; mi < 4; mi++) ldsm4(a[mi], Xb + rA[mi] + ka);
            uint32_t b[4][4];
#pragma unroll
            for (int t = 0; t < 4; t++) ldsm4(b[t], Xb + rB[t] + kb);
#pragma unroll
            for (int mi = 0; mi < 4; mi++)
#pragma unroll
                for (int nf = 0; nf < 8; nf++)
                    mma_f16(acc[mi][nf], a[mi], &b[nf >> 1][(nf & 1) * 2]);
        }
    }

    if (mode == 0) {
#pragma unroll
        for (int mi = 0; mi < 4; mi++)
#pragma unroll
            for (int rr = 0; rr < 2; rr++) {
                size_t row = mBase + wm * 64 + mi * 16 + g + rr * 8;
                int bb = (int)(row >> 11), t = (int)(row & 2047);
#pragma unroll
                for (int nf = 0; nf < 8; nf++) {
                    int c = nBase + wn * 64 + nf * 8 + 2 * q;
                    int h = c >> 6, cc = c & 63;
                    float v0 = acc[mi][nf][2 * rr + 0];
                    float v1 = acc[mi][nf][2 * rr + 1];
                    if (z == 2) {   // V transposed: [B,H,64,T]
                        size_t o = (((size_t)bb * H_ + h) * DH_ + cc) * T_ + t;
                        g_v[o]      = __float2half_rn(v0);
                        g_v[o + T_] = __float2half_rn(v1);
                    } else {
                        __half* outq = (z == 0) ? g_q : g_k;
                        size_t o = (((size_t)bb * H_ + h) * T_ + t) * DH_ + cc;
                        *reinterpret_cast<__half2*>(outq + o) = __floats2half2_rn(v0, v1);
                    }
                }
            }
    } else {
#pragma unroll
        for (int mi = 0; mi < 4; mi++)
#pragma unroll
            for (int rr = 0; rr < 2; rr++) {
                size_t row = mBase + wm * 64 + mi * 16 + g + rr * 8;
#pragma unroll
                for (int nf = 0; nf < 8; nf++) {
                    int c = nBase + wn * 64 + nf * 8 + 2 * q;
                    size_t o = row * DM_ + c;
                    out_param[o]     = acc[mi][nf][2 * rr + 0] + bias[c];
                    out_param[o + 1] = acc[mi][nf][2 * rr + 1] + bias[c + 1];
                }
            }
    }
}

// ---------------------------------------------------------------------------
// Causal flash attention v7 (PROVEN round-14): 16 Q rows/warp, 2 CTAs/SM.
// grid (T/128=16, B*H=64), 256 threads, 128 regs.
// ---------------------------------------------------------------------------
constexpr int AT_BYTES  = 64 * 128;             // 8 KB per tile
constexpr int ASTAGE_B  = 2 * AT_BYTES;         // 16 KB (K + V)
constexpr int ATT_SMEM  = NSTG * ASTAGE_B;      // 48 KB -> 2 CTAs/SM

__device__ __forceinline__ void attn_load_kv(
    uint32_t smBase, int buf, const __half* __restrict__ Kg, const __half* __restrict__ Vt,
    int j, int tid)
{
    const uint32_t kb = smBase + buf * ASTAGE_B;
    const uint32_t vb = kb + AT_BYTES;
#pragma unroll
    for (int i = 0; i < 2; i++) {
        int idx = tid + i * 256;
        int r = idx >> 3, c = idx & 7;
        cp16(kb + sw128(r * 128 + c * 16), Kg + (size_t)(j * 64 + r) * DH_ + c * 8);
        cp16(vb + sw128(r * 128 + c * 16), Vt + (size_t)r * T_ + j * 64 + c * 8);
    }
    cp_commit();
}

__global__ void __launch_bounds__(256, 2) attn7()
{
    extern __shared__ __half smh[];
    const uint32_t smBase = smem_u32(smh);
    const int tid  = threadIdx.x;
    const int lane = tid & 31, w = tid >> 5;
    const int g = lane >> 2, q = lane & 3;
    const int r7 = lane & 7, sub = lane >> 3;
    const uint32_t xm = (uint32_t)r7 << 4;
    const uint32_t bksel = (uint32_t)(sub & 1) * 16;
    const int bx = (int)gridDim.x - 1 - (int)blockIdx.x;   // heavy CTAs first
    const int bh = blockIdx.y;
    const int qb = bx * 128;
    const float SCL = 0.18033688f;   // 0.125 * log2(e)

    uint32_t rT[4];
#pragma unroll
    for (int t = 0; t < 4; t++)
        rT[t] = (uint32_t)(t * 16 + r7 + (sub >> 1) * 8) * 128;

    const __half* Qg = g_q + ((size_t)bh * T_ + qb) * DH_;
    const __half* Kg = g_k + (size_t)bh * T_ * DH_;
    const __half* Vt = g_v + (size_t)bh * DH_ * T_;        // [64][T]

    // Q fragments: 16 rows per warp, scaled, fp16
    uint32_t qf[4][4];
    {
        const int r = w * 16 + g;
#pragma unroll
        for (int ks = 0; ks < 4; ks++) {
            const int kk = ks * 16 + 2 * q;
#pragma unroll
            for (int p = 0; p < 4; p++) {
                int rr = (p & 1) ? r + 8 : r;
                int kc = kk + ((p >> 1) ? 8 : 0);
                float2 f = __half22float2(
                    *reinterpret_cast<const __half2*>(Qg + (size_t)rr * DH_ + kc));
                qf[ks][p] = pack_h2(f.x * SCL, f.y * SCL);
            }
        }
    }

    float o_acc[8][4];
#pragma unroll
    for (int j = 0; j < 8; j++)
#pragma unroll
        for (int r = 0; r < 4; r++) o_acc[j][r] = 0.f;
    float lsum0 = 0.f, lsum1 = 0.f;

    const int nkb = 2 * bx + 2;
    attn_load_kv(smBase, 0, Kg, Vt, 0, tid);
    attn_load_kv(smBase, 1, Kg, Vt, 1, tid);

#pragma unroll 1
    for (int j = 0; j < nkb; j++) {
        if (j + 1 < nkb) cp_wait<1>(); else cp_wait<0>();
        __syncthreads();
        if (j + 2 < nkb) attn_load_kv(smBase, (j + 2) % NSTG, Kg, Vt, j + 2, tid);

        const uint32_t Kb = smBase + (j % NSTG) * ASTAGE_B;
        const uint32_t Vb = Kb + AT_BYTES;

        // S = (Q*scl) K^T : per warp 16x64 (log2 domain)
        float s[8][4];
#pragma unroll
        for (int jj = 0; jj < 8; jj++)
#pragma unroll
            for (int r = 0; r < 4; r++) s[jj][r] = 0.f;

#pragma unroll
        for (int ks = 0; ks < 4; ks++) {
            const uint32_t kb = (ks * 32 + bksel) ^ xm;
            uint32_t b[4][4];
#pragma unroll
            for (int t = 0; t < 4; t++) ldsm4(b[t], Kb + rT[t] + kb);
#pragma unroll
            for (int nf = 0; nf < 8; nf++)
                mma_f16(s[nf], qf[ks], &b[nf >> 1][(nf & 1) * 2]);
        }

        // mask (diagonal blocks only) + shift-free exp2 + partial sums
        const bool need_mask = (j * 64 + 63) > (qb + w * 16);
        if (need_mask) {
            const int row0 = qb + w * 16 + g;
#pragma unroll
            for (int nf = 0; nf < 8; nf++) {
                int c0 = j * 64 + nf * 8 + 2 * q;
                if (c0     > row0)     s[nf][0] = -INFINITY;
                if (c0 + 1 > row0)     s[nf][1] = -INFINITY;
                if (c0     > row0 + 8) s[nf][2] = -INFINITY;
                if (c0 + 1 > row0 + 8) s[nf][3] = -INFINITY;
            }
        }
#pragma unroll
        for (int nf = 0; nf < 8; nf++) {
            s[nf][0] = fexp2(s[nf][0]);
            s[nf][1] = fexp2(s[nf][1]);
            s[nf][2] = fexp2(s[nf][2]);
            s[nf][3] = fexp2(s[nf][3]);
            lsum0 += s[nf][0] + s[nf][1];
            lsum1 += s[nf][2] + s[nf][3];
        }

        // O += P V : P packed in-thread (C-layout == A-layout at k16)
#pragma unroll
        for (int ks = 0; ks < 4; ks++) {
            const uint32_t kb = (ks * 32 + bksel) ^ xm;
            uint32_t b[4][4];
#pragma unroll
            for (int t = 0; t < 4; t++) ldsm4(b[t], Vb + rT[t] + kb);
            uint32_t a[4];
            a[0] = pack_h2(s[2 * ks][0],     s[2 * ks][1]);
            a[1] = pack_h2(s[2 * ks][2],     s[2 * ks][3]);
            a[2] = pack_h2(s[2 * ks + 1][0], s[2 * ks + 1][1]);
            a[3] = pack_h2(s[2 * ks + 1][2], s[2 * ks + 1][3]);
#pragma unroll
            for (int dn = 0; dn < 8; dn++)
                mma_f16(o_acc[dn], a, &b[dn >> 1][(dn & 1) * 2]);
        }
    }

    // epilogue: quad reduce of row sums, normalize, write g_o [B,T,H*64]
    const int bb = bh >> 4, h = bh & 15;
    lsum0 += __shfl_xor_sync(0xffffffffu, lsum0, 1);
    lsum0 += __shfl_xor_sync(0xffffffffu, lsum0, 2);
    lsum1 += __shfl_xor_sync(0xffffffffu, lsum1, 1);
    lsum1 += __shfl_xor_sync(0xffffffffu, lsum1, 2);
    const float inv0 = 1.f / lsum0, inv1 = 1.f / lsum1;
    const int t0 = qb + w * 16 + g;
#pragma unroll
    for (int dn = 0; dn < 8; dn++) {
        int col = h * DH_ + dn * 8 + 2 * q;
        size_t o0 = ((size_t)bb * T_ + t0) * DM_ + col;
        size_t o1 = o0 + (size_t)8 * DM_;
        *reinterpret_cast<__half2*>(g_o + o0) =
            __floats2half2_rn(o_acc[dn][0] * inv0, o_acc[dn][1] * inv0);
        *reinterpret_cast<__half2*>(g_o + o1) =
            __floats2half2_rn(o_acc[dn][2] * inv1, o_acc[dn][3] * inv1);
    }
}

}  // namespace

extern "C" void kernel_launch(void* const* d_in, const int* in_sizes, int n_in,
                              void* d_out, int out_size)
{
    (void)in_sizes; (void)n_in; (void)out_size;
    const float* x  = (const float*)d_in[0];
    const float* Wq = (const float*)d_in[1];
    const float* Wk = (const float*)d_in[2];
    const float* Wv = (const float*)d_in[3];
    const float* Wo = (const float*)d_in[4];
    const float* bo = (const float*)d_in[5];
    float* out = (float*)d_out;

    cudaFuncSetAttribute(gemm6, cudaFuncAttributeMaxDynamicSharedMemorySize, GEMM_SMEM);
    cudaFuncSetAttribute(attn7, cudaFuncAttributeMaxDynamicSharedMemorySize, ATT_SMEM);

    // fp16 conversions: x; all weights transposed to [N][K]
    round_x<<<(M_ * DM_ / 4 + 255) / 256, 256>>>(x, M_ * DM_ / 4);
    transpose_all<<<4096, 256>>>(Wq, Wk, Wv, Wo);

    // fused QKV projections (V written transposed), CTA tile 128x256
    gemm6<<<dim3(M_ / 128, DM_ / 256, 3), 256, GEMM_SMEM>>>(0, nullptr, nullptr);
    // causal flash attention: 128 Q rows/CTA, 2 CTAs/SM
    attn7<<<dim3(T_ / 128, B_ * H_), 256, ATT_SMEM>>>();
    // output projection + bias (fp32 out)
    gemm6<<<dim3(M_ / 128, DM_ / 256, 1), 256, GEMM_SMEM>>>(1, bo, out);
}

// round 16
// speedup vs baseline: 1.1435x; 1.1435x over previous
#include <cuda_runtime.h>
#include <cuda_fp16.h>
#include <cstdint>
#include <math.h>

namespace {
constexpr int B_  = 4;
constexpr int T_  = 2048;
constexpr int DM_ = 1024;
constexpr int H_  = 16;
constexpr int DH_ = 64;
constexpr int M_  = B_ * T_;     // 8192

// Scratch (device globals: allocation-free rule). fp16.
__device__ __half g_x  [(size_t)M_ * DM_];
__device__ __half g_wqT[(size_t)DM_ * DM_];  // [n][k]
__device__ __half g_wkT[(size_t)DM_ * DM_];
__device__ __half g_wvT[(size_t)DM_ * DM_];
__device__ __half g_woT[(size_t)DM_ * DM_];
__device__ __half g_q  [(size_t)M_ * DM_];   // [B,H,T,64]
__device__ __half g_k  [(size_t)M_ * DM_];
__device__ __half g_v  [(size_t)M_ * DM_];   // [B,H,64,T] (transposed for PV)
__device__ __half g_o  [(size_t)M_ * DM_];   // [B,T,H*64]

__device__ __forceinline__ float fexp2(float x) {
    float y;
    asm("ex2.approx.f32 %0, %1;" : "=f"(y) : "f"(x));
    return y;
}
__device__ __forceinline__ void mma_f16(float* c, const uint32_t* a, const uint32_t* b) {
    asm volatile(
        "mma.sync.aligned.m16n8k16.row.col.f32.f16.f16.f32 "
        "{%0,%1,%2,%3}, {%4,%5,%6,%7}, {%8,%9}, {%0,%1,%2,%3};\n"
        : "+f"(c[0]), "+f"(c[1]), "+f"(c[2]), "+f"(c[3])
        : "r"(a[0]), "r"(a[1]), "r"(a[2]), "r"(a[3]), "r"(b[0]), "r"(b[1]));
}
__device__ __forceinline__ void ldsm4(uint32_t* r, uint32_t addr) {
    asm volatile("ldmatrix.sync.aligned.m8n8.x4.shared.b16 {%0,%1,%2,%3}, [%4];"
        : "=r"(r[0]), "=r"(r[1]), "=r"(r[2]), "=r"(r[3]) : "r"(addr));
}
__device__ __forceinline__ uint32_t pack_h2(float x, float y) {
    __half2 h = __floats2half2_rn(x, y);
    return *reinterpret_cast<uint32_t*>(&h);
}
__device__ __forceinline__ uint32_t smem_u32(const void* p) {
    return (uint32_t)__cvta_generic_to_shared(p);
}
__device__ __forceinline__ void cp16(uint32_t dst, const void* src) {
    asm volatile("cp.async.cg.shared.global [%0], [%1], 16;\n" :: "r"(dst), "l"(src));
}
__device__ __forceinline__ void cp_commit() {
    asm volatile("cp.async.commit_group;\n");
}
template <int N>
__device__ __forceinline__ void cp_wait() {
    asm volatile("cp.async.wait_group %0;\n" :: "n"(N));
}
__device__ __forceinline__ uint32_t sw128(uint32_t off) {
    return off ^ ((off >> 3) & 0x70);
}

// ---------------------------------------------------------------------------
// Fused prep: blocks [0, 8192)   -> x fp32->fp16 copy
//             blocks [8192,12288)-> weight transpose [K,N]->[N,K] fp16
// ---------------------------------------------------------------------------
__global__ void __launch_bounds__(256) prep_all(
    const float* __restrict__ x,
    const float* __restrict__ Wq, const float* __restrict__ Wk,
    const float* __restrict__ Wv, const float* __restrict__ Wo)
{
    const int bid = blockIdx.x;
    if (bid < 8192) {
        int i = bid * 256 + threadIdx.x;     // n4 = M_*DM_/4 = 2M
        float4 v = reinterpret_cast<const float4*>(x)[i];
        reinterpret_cast<__half2*>(g_x)[2 * i]     = __floats2half2_rn(v.x, v.y);
        reinterpret_cast<__half2*>(g_x)[2 * i + 1] = __floats2half2_rn(v.z, v.w);
        return;
    }
    __shared__ float tl[32][33];
    const int tx = threadIdx.x & 31, ty = threadIdx.x >> 5;
    const int tb = bid - 8192;
    int which, h, d0, n0;
    if (tb < 3072) {
        which = tb >> 10;
        int r = tb & 1023;
        d0 = (r & 31) * 32;
        n0 = ((r >> 5) & 1) * 32;
        h  = r >> 6;
    } else {
        which = 3;
        int r = tb - 3072;
        d0 = (r & 31) * 32;
        n0 = (r >> 5) * 32;
        h  = 0;
    }
    const float* in = (which == 0) ? Wq : (which == 1) ? Wk :
                      (which == 2) ? Wv : Wo;
    __half* dst = (which == 0) ? g_wqT : (which == 1) ? g_wkT :
                  (which == 2) ? g_wvT : g_woT;
    const int ldn = (which == 3) ? DM_ : DH_;
    const float* src = (which == 3) ? in : in + (size_t)h * DM_ * DH_;

#pragma unroll
    for (int i = 0; i < 4; i++) {
        int d = d0 + ty + i * 8;
        tl[ty + i * 8][tx] = src[(size_t)d * ldn + n0 + tx];
    }
    __syncthreads();
    const int nb = (which == 3) ? n0 : (h * DH_ + n0);
#pragma unroll
    for (int i = 0; i < 4; i++) {
        int n = ty + i * 8;
        dst[(size_t)(nb + n) * DM_ + d0 + tx] = __float2half_rn(tl[tx][n]);
    }
}

// ---------------------------------------------------------------------------
// fp16 GEMM (PROVEN round-8/14): tile 128x128, warp 32x64, k-chunk 64,
// 3-stage cp.async, SW128 + ldmatrix, 2 CTAs/SM (<=128 regs).
// mode 0: QKV. grid (64, 8, 3). z: WqT/WkT/WvT -> g_q / g_k / g_v(transposed)
// mode 1: out projection. grid (64, 8, 1). X=g_o, W=g_woT, out fp32 + bias.
// ---------------------------------------------------------------------------
constexpr int NSTG = 3;
constexpr int GT_BYTES  = 128 * 128;            // 16 KB per tile
constexpr int GSTAGE_B  = 2 * GT_BYTES;         // 32 KB (X + W)
constexpr int GEMM_SMEM = NSTG * GSTAGE_B;      // 96 KB -> 2 CTAs/SM
constexpr int CHUNK = 64;
constexpr int NCHUNK = DM_ / CHUNK;             // 16

__device__ __forceinline__ void gemm_load_chunk(
    uint32_t smBase, int buf, const __half* __restrict__ X, const __half* __restrict__ Wt,
    size_t mBase, int nBase, int k0, int tid)
{
    const uint32_t xb = smBase + buf * GSTAGE_B;
    const uint32_t wb = xb + GT_BYTES;
#pragma unroll
    for (int i = 0; i < 4; i++) {
        int idx = tid + i * 256;
        int r = idx >> 3, c = idx & 7;
        cp16(xb + sw128(r * 128 + c * 16), X + (mBase + r) * DM_ + k0 + c * 8);
        cp16(wb + sw128(r * 128 + c * 16), Wt + (size_t)(nBase + r) * DM_ + k0 + c * 8);
    }
    cp_commit();
}

__global__ void __launch_bounds__(256, 2) gemm5(
    int mode, const float* __restrict__ bias, float* __restrict__ out_param)
{
    extern __shared__ __half smh[];
    const uint32_t smBase = smem_u32(smh);
    const int tid  = threadIdx.x;
    const int lane = tid & 31, wid = tid >> 5;
    const int wm = wid >> 1, wn = wid & 1;
    const int g = lane >> 2, q = lane & 3;
    const int r7 = lane & 7, sub = lane >> 3;
    const uint32_t xm = (uint32_t)r7 << 4;
    const uint32_t aksel = (uint32_t)(sub >> 1) * 16;
    const uint32_t bksel = (uint32_t)(sub & 1) * 16;
    const size_t mBase = (size_t)blockIdx.x * 128;
    const int nBase = blockIdx.y * 128;
    const int z  = blockIdx.z;

    uint32_t rA[2], rB[4];
#pragma unroll
    for (int mf = 0; mf < 2; mf++)
        rA[mf] = (uint32_t)(wm * 32 + mf * 16 + r7 + (sub & 1) * 8) * 128;
#pragma unroll
    for (int t = 0; t < 4; t++)
        rB[t] = (uint32_t)(wn * 64 + t * 16 + r7 + (sub >> 1) * 8) * 128;

    const __half* X  = (mode == 0) ? g_x : g_o;
    const __half* Wt = (mode == 0) ? ((z == 0) ? g_wqT : (z == 1) ? g_wkT : g_wvT) : g_woT;

    float acc[2][8][4];
#pragma unroll
    for (int i = 0; i < 2; i++)
#pragma unroll
        for (int j = 0; j < 8; j++)
#pragma unroll
            for (int r = 0; r < 4; r++) acc[i][j][r] = 0.f;

    gemm_load_chunk(smBase, 0, X, Wt, mBase, nBase, 0, tid);
    gemm_load_chunk(smBase, 1, X, Wt, mBase, nBase, CHUNK, tid);

#pragma unroll 1
    for (int i = 0; i < NCHUNK; i++) {
        if (i + 1 < NCHUNK) cp_wait<1>(); else cp_wait<0>();
        __syncthreads();
        if (i + 2 < NCHUNK)
            gemm_load_chunk(smBase, (i + 2) % NSTG, X, Wt, mBase, nBase, (i + 2) * CHUNK, tid);

        const uint32_t Xb = smBase + (i % NSTG) * GSTAGE_B;
        const uint32_t Wb = Xb + GT_BYTES;
#pragma unroll
        for (int ks = 0; ks < 4; ks++) {
            const uint32_t ka = (ks * 32 + aksel) ^ xm;
            const uint32_t kb = (ks * 32 + bksel) ^ xm;
            uint32_t a[2][4];
            ldsm4(a[0], Xb + rA[0] + ka);
            ldsm4(a[1], Xb + rA[1] + ka);
            uint32_t b[4][4];
#pragma unroll
            for (int t = 0; t < 4; t++) ldsm4(b[t], Wb + rB[t] + kb);
#pragma unroll
            for (int mf = 0; mf < 2; mf++)
#pragma unroll
                for (int nf = 0; nf < 8; nf++)
                    mma_f16(acc[mf][nf], a[mf], &b[nf >> 1][(nf & 1) * 2]);
        }
    }

    if (mode == 0) {
#pragma unroll
        for (int mf = 0; mf < 2; mf++)
#pragma unroll
            for (int rr = 0; rr < 2; rr++) {
                size_t row = mBase + wm * 32 + mf * 16 + g + rr * 8;
                int bb = (int)(row >> 11), t = (int)(row & 2047);
#pragma unroll
                for (int nf = 0; nf < 8; nf++) {
                    int c = nBase + wn * 64 + nf * 8 + 2 * q;
                    int h = c >> 6, cc = c & 63;
                    float v0 = acc[mf][nf][2 * rr + 0];
                    float v1 = acc[mf][nf][2 * rr + 1];
                    if (z == 2) {   // V transposed: [B,H,64,T]
                        size_t o = (((size_t)bb * H_ + h) * DH_ + cc) * T_ + t;
                        g_v[o]      = __float2half_rn(v0);
                        g_v[o + T_] = __float2half_rn(v1);
                    } else {
                        __half* outq = (z == 0) ? g_q : g_k;
                        size_t o = (((size_t)bb * H_ + h) * T_ + t) * DH_ + cc;
                        *reinterpret_cast<__half2*>(outq + o) = __floats2half2_rn(v0, v1);
                    }
                }
            }
    } else {
#pragma unroll
        for (int mf = 0; mf < 2; mf++)
#pragma unroll
            for (int rr = 0; rr < 2; rr++) {
                size_t row = mBase + wm * 32 + mf * 16 + g + rr * 8;
#pragma unroll
                for (int nf = 0; nf < 8; nf++) {
                    int c = nBase + wn * 64 + nf * 8 + 2 * q;
                    size_t o = row * DM_ + c;
                    out_param[o]     = acc[mf][nf][2 * rr + 0] + bias[c];
                    out_param[o + 1] = acc[mf][nf][2 * rr + 1] + bias[c + 1];
                }
            }
    }
}

// ---------------------------------------------------------------------------
// Causal flash attention v7 (PROVEN round-14): 16 Q rows/warp, 2 CTAs/SM.
// grid (T/128=16, B*H=64), 256 threads, 128 regs.
// ---------------------------------------------------------------------------
constexpr int AT_BYTES  = 64 * 128;             // 8 KB per tile
constexpr int ASTAGE_B  = 2 * AT_BYTES;         // 16 KB (K + V)
constexpr int ATT_SMEM  = NSTG * ASTAGE_B;      // 48 KB -> 2 CTAs/SM

__device__ __forceinline__ void attn_load_kv(
    uint32_t smBase, int buf, const __half* __restrict__ Kg, const __half* __restrict__ Vt,
    int j, int tid)
{
    const uint32_t kb = smBase + buf * ASTAGE_B;
    const uint32_t vb = kb + AT_BYTES;
#pragma unroll
    for (int i = 0; i < 2; i++) {
        int idx = tid + i * 256;
        int r = idx >> 3, c = idx & 7;
        cp16(kb + sw128(r * 128 + c * 16), Kg + (size_t)(j * 64 + r) * DH_ + c * 8);
        cp16(vb + sw128(r * 128 + c * 16), Vt + (size_t)r * T_ + j * 64 + c * 8);
    }
    cp_commit();
}

__global__ void __launch_bounds__(256, 2) attn7()
{
    extern __shared__ __half smh[];
    const uint32_t smBase = smem_u32(smh);
    const int tid  = threadIdx.x;
    const int lane = tid & 31, w = tid >> 5;
    const int g = lane >> 2, q = lane & 3;
    const int r7 = lane & 7, sub = lane >> 3;
    const uint32_t xm = (uint32_t)r7 << 4;
    const uint32_t bksel = (uint32_t)(sub & 1) * 16;
    const int bx = (int)gridDim.x - 1 - (int)blockIdx.x;   // heavy CTAs first
    const int bh = blockIdx.y;
    const int qb = bx * 128;
    const float SCL = 0.18033688f;   // 0.125 * log2(e)

    uint32_t rT[4];
#pragma unroll
    for (int t = 0; t < 4; t++)
        rT[t] = (uint32_t)(t * 16 + r7 + (sub >> 1) * 8) * 128;

    const __half* Qg = g_q + ((size_t)bh * T_ + qb) * DH_;
    const __half* Kg = g_k + (size_t)bh * T_ * DH_;
    const __half* Vt = g_v + (size_t)bh * DH_ * T_;        // [64][T]

    // Q fragments: 16 rows per warp, scaled, fp16
    uint32_t qf[4][4];
    {
        const int r = w * 16 + g;
#pragma unroll
        for (int ks = 0; ks < 4; ks++) {
            const int kk = ks * 16 + 2 * q;
#pragma unroll
            for (int p = 0; p < 4; p++) {
                int rr = (p & 1) ? r + 8 : r;
                int kc = kk + ((p >> 1) ? 8 : 0);
                float2 f = __half22float2(
                    *reinterpret_cast<const __half2*>(Qg + (size_t)rr * DH_ + kc));
                qf[ks][p] = pack_h2(f.x * SCL, f.y * SCL);
            }
        }
    }

    float o_acc[8][4];
#pragma unroll
    for (int j = 0; j < 8; j++)
#pragma unroll
        for (int r = 0; r < 4; r++) o_acc[j][r] = 0.f;
    float lsum0 = 0.f, lsum1 = 0.f;

    const int nkb = 2 * bx + 2;
    attn_load_kv(smBase, 0, Kg, Vt, 0, tid);
    attn_load_kv(smBase, 1, Kg, Vt, 1, tid);

#pragma unroll 1
    for (int j = 0; j < nkb; j++) {
        if (j + 1 < nkb) cp_wait<1>(); else cp_wait<0>();
        __syncthreads();
        if (j + 2 < nkb) attn_load_kv(smBase, (j + 2) % NSTG, Kg, Vt, j + 2, tid);

        const uint32_t Kb = smBase + (j % NSTG) * ASTAGE_B;
        const uint32_t Vb = Kb + AT_BYTES;

        // S = (Q*scl) K^T : per warp 16x64 (log2 domain)
        float s[8][4];
#pragma unroll
        for (int jj = 0; jj < 8; jj++)
#pragma unroll
            for (int r = 0; r < 4; r++) s[jj][r] = 0.f;

#pragma unroll
        for (int ks = 0; ks < 4; ks++) {
            const uint32_t kb = (ks * 32 + bksel) ^ xm;
            uint32_t b[4][4];
#pragma unroll
            for (int t = 0; t < 4; t++) ldsm4(b[t], Kb + rT[t] + kb);
#pragma unroll
            for (int nf = 0; nf < 8; nf++)
                mma_f16(s[nf], qf[ks], &b[nf >> 1][(nf & 1) * 2]);
        }

        // mask (diagonal blocks only) + shift-free exp2 + partial sums
        const bool need_mask = (j * 64 + 63) > (qb + w * 16);
        if (need_mask) {
            const int row0 = qb + w * 16 + g;
#pragma unroll
            for (int nf = 0; nf < 8; nf++) {
                int c0 = j * 64 + nf * 8 + 2 * q;
                if (c0     > row0)     s[nf][0] = -INFINITY;
                if (c0 + 1 > row0)     s[nf][1] = -INFINITY;
                if (c0     > row0 + 8) s[nf][2] = -INFINITY;
                if (c0 + 1 > row0 + 8) s[nf][3] = -INFINITY;
            }
        }
#pragma unroll
        for (int nf = 0; nf < 8; nf++) {
            s[nf][0] = fexp2(s[nf][0]);
            s[nf][1] = fexp2(s[nf][1]);
            s[nf][2] = fexp2(s[nf][2]);
            s[nf][3] = fexp2(s[nf][3]);
            lsum0 += s[nf][0] + s[nf][1];
            lsum1 += s[nf][2] + s[nf][3];
        }

        // O += P V : P packed in-thread (C-layout == A-layout at k16)
#pragma unroll
        for (int ks = 0; ks < 4; ks++) {
            const uint32_t kb = (ks * 32 + bksel) ^ xm;
            uint32_t b[4][4];
#pragma unroll
            for (int t = 0; t < 4; t++) ldsm4(b[t], Vb + rT[t] + kb);
            uint32_t a[4];
            a[0] = pack_h2(s[2 * ks][0],     s[2 * ks][1]);
            a[1] = pack_h2(s[2 * ks][2],     s[2 * ks][3]);
            a[2] = pack_h2(s[2 * ks + 1][0], s[2 * ks + 1][1]);
            a[3] = pack_h2(s[2 * ks + 1][2], s[2 * ks + 1][3]);
#pragma unroll
            for (int dn = 0; dn < 8; dn++)
                mma_f16(o_acc[dn], a, &b[dn >> 1][(dn & 1) * 2]);
        }
    }

    // epilogue: quad reduce of row sums, normalize, write g_o [B,T,H*64]
    const int bb = bh >> 4, h = bh & 15;
    lsum0 += __shfl_xor_sync(0xffffffffu, lsum0, 1);
    lsum0 += __shfl_xor_sync(0xffffffffu, lsum0, 2);
    lsum1 += __shfl_xor_sync(0xffffffffu, lsum1, 1);
    lsum1 += __shfl_xor_sync(0xffffffffu, lsum1, 2);
    const float inv0 = 1.f / lsum0, inv1 = 1.f / lsum1;
    const int t0 = qb + w * 16 + g;
#pragma unroll
    for (int dn = 0; dn < 8; dn++) {
        int col = h * DH_ + dn * 8 + 2 * q;
        size_t o0 = ((size_t)bb * T_ + t0) * DM_ + col;
        size_t o1 = o0 + (size_t)8 * DM_;
        *reinterpret_cast<__half2*>(g_o + o0) =
            __floats2half2_rn(o_acc[dn][0] * inv0, o_acc[dn][1] * inv0);
        *reinterpret_cast<__half2*>(g_o + o1) =
            __floats2half2_rn(o_acc[dn][2] * inv1, o_acc[dn][3] * inv1);
    }
}

}  // namespace

extern "C" void kernel_launch(void* const* d_in, const int* in_sizes, int n_in,
                              void* d_out, int out_size)
{
    (void)in_sizes; (void)n_in; (void)out_size;
    const float* x  = (const float*)d_in[0];
    const float* Wq = (const float*)d_in[1];
    const float* Wk = (const float*)d_in[2];
    const float* Wv = (const float*)d_in[3];
    const float* Wo = (const float*)d_in[4];
    const float* bo = (const float*)d_in[5];
    float* out = (float*)d_out;

    cudaFuncSetAttribute(gemm5, cudaFuncAttributeMaxDynamicSharedMemorySize, GEMM_SMEM);
    cudaFuncSetAttribute(attn7, cudaFuncAttributeMaxDynamicSharedMemorySize, ATT_SMEM);

    // single fused prep launch: x fp16 copy + all weight transposes
    prep_all<<<12288, 256>>>(x, Wq, Wk, Wv, Wo);

    // fused QKV projections (V written transposed), proven 128x128 GEMM
    gemm5<<<dim3(M_ / 128, DM_ / 128, 3), 256, GEMM_SMEM>>>(0, nullptr, nullptr);
    // causal flash attention: 128 Q rows/CTA, 2 CTAs/SM
    attn7<<<dim3(T_ / 128, B_ * H_), 256, ATT_SMEM>>>();
    // output projection + bias (fp32 out)
    gemm5<<<dim3(M_ / 128, DM_ / 128, 1), 256, GEMM_SMEM>>>(1, bo, out);
}